// round 16
// baseline (speedup 1.0000x reference)
#include <cuda_runtime.h>
#include <cuda_bf16.h>
#include <cstdint>
#include <math.h>
#define HD 1024
#define NBS 64
#define F_XB 0UL
#define F_T  (F_XB+33554432UL)
#define F_U  (F_T+6291456UL)
#define F_TOT (F_U+6291456UL)
__device__ float g_f[F_TOT];
__device__ __nv_bfloat16 g_b[213909504UL];
__device__ float sp_part3[3*NBS*HD];
__device__ float sp_u3[3*HD], sp_v3[3*HD], sp_w3[3*HD];
__device__ float sp_nu[3*64];
__device__ float sp_nv[3*4];
__device__ float d_rsigma[3];
__device__ unsigned bar_c3[3] = {0,0,0}, bar_g3[3] = {0,0,0};

__device__ __forceinline__ void gbar3(int g) {
    __syncthreads(); __threadfence();
    if (threadIdx.x == 0) {
        unsigned gen = atomicAdd(&bar_g3[g], 0u);
        if (atomicAdd(&bar_c3[g], 1u) == NBS - 1u) {
            bar_c3[g] = 0u; __threadfence(); atomicExch(&bar_g3[g], gen + 1u);
        } else while (atomicAdd(&bar_g3[g], 0u) == gen) __nanosleep(64);
    }
    __syncthreads();
}

// fused-norm power iteration; 3 matrices in parallel (group g = bid/64)
__global__ void __launch_bounds__(256) spectral3(const float* __restrict__ WA,
    const float* __restrict__ WB, const float* __restrict__ WC) {
    __shared__ float red[256];
    __shared__ float wsum[8];
    const int tid = threadIdx.x, g = blockIdx.x >> 6, lb = blockIdx.x & 63;
    const int gtid = lb*256 + tid;
    const float* W = (g==0) ? WA : ((g==1) ? WB : WC);
    float* up = sp_u3 + g*HD;
    float* vp = sp_v3 + g*HD;
    float* wp = sp_w3 + g*HD;
    float* part = sp_part3 + (size_t)g*NBS*HD;
    if (gtid < HD) up[gtid] = 0.03125f;
    if (lb == 0 && tid < 64) sp_nu[g*64+tid] = 1.f/64.f;  // ||u0||^2 = 1
    gbar3(g);
    for (int it = 0; it <= 10; it++) {
        { // phase1: partial W^T u_raw
            const int i0 = lb*16;
            float a0=0,a1=0,a2=0,a3=0;
            for (int i = i0; i < i0+16; i++) {
                float ui = __ldcg(&up[i]);
                const float* Wr = W + (size_t)i*HD;
                a0 += Wr[tid]*ui; a1 += Wr[tid+256]*ui;
                a2 += Wr[tid+512]*ui; a3 += Wr[tid+768]*ui;
            }
            part[lb*HD+tid]=a0; part[lb*HD+tid+256]=a1;
            part[lb*HD+tid+512]=a2; part[lb*HD+tid+768]=a3;
        }
        gbar3(g);
        // phase2: reduce -> v_raw (scaled by 1/||u_raw||) + v-norm partials
        float vloc = 0.f;
        if (gtid < HD) {
            float s=0;
            for (int b=0;b<NBS;b++) s += __ldcg(&part[b*HD+gtid]);
            float nu=0;
            #pragma unroll 8
            for (int b=0;b<NBS;b++) nu += __ldcg(&sp_nu[g*64+b]);
            float su = 1.f/(sqrtf(nu)+1e-12f);
            vloc = s*su;
            vp[gtid] = vloc;
        }
        if (lb < 4) {
            red[tid] = vloc*vloc; __syncthreads();
            for (int st=128;st>0;st>>=1){ if(tid<st) red[tid]+=red[tid+st]; __syncthreads(); }
            if (tid==0) sp_nv[g*4+lb] = red[0];
        }
        gbar3(g);
        if (it == 10) break;
        { // phase3: u_raw = (W v_raw)*sv + u-norm partials
            float nv = __ldcg(&sp_nv[g*4+0])+__ldcg(&sp_nv[g*4+1])
                     + __ldcg(&sp_nv[g*4+2])+__ldcg(&sp_nv[g*4+3]);
            float sv = 1.f/(sqrtf(nv)+1e-12f);
            const int warp = gtid>>5, lane = gtid&31, wl = tid>>5;
            float u2 = 0.f;
            for (int i = warp; i < HD; i += (NBS*256)/32) {
                const float* Wr = W + (size_t)i*HD;
                float s=0;
                for (int j=lane;j<HD;j+=32) s += Wr[j]*__ldcg(&vp[j]);
                #pragma unroll
                for (int o=16;o;o>>=1) s += __shfl_xor_sync(0xffffffffu,s,o);
                if (lane==0) { float uu = s*sv; up[i]=uu; u2 += uu*uu; }
            }
            if (lane==0) wsum[wl] = u2;
            __syncthreads();
            if (tid==0) {
                float s=0;
                #pragma unroll
                for (int q=0;q<8;q++) s += wsum[q];
                sp_nu[g*64+lb] = s;
            }
        }
        gbar3(g);
    }
    { // w = W v_hat
        float nv = __ldcg(&sp_nv[g*4+0])+__ldcg(&sp_nv[g*4+1])
                 + __ldcg(&sp_nv[g*4+2])+__ldcg(&sp_nv[g*4+3]);
        float sv = 1.f/(sqrtf(nv)+1e-12f);
        const int warp = gtid>>5, lane = gtid&31;
        for (int i = warp; i < HD; i += (NBS*256)/32) {
            const float* Wr = W + (size_t)i*HD;
            float s=0;
            for (int j=lane;j<HD;j+=32) s += Wr[j]*__ldcg(&vp[j]);
            #pragma unroll
            for (int o=16;o;o>>=1) s += __shfl_xor_sync(0xffffffffu,s,o);
            if (lane==0) wp[i] = s*sv;
        }
    }
    gbar3(g);
    if (lb == 0) {
        float nu=0;
        #pragma unroll 8
        for (int b=0;b<NBS;b++) nu += __ldcg(&sp_nu[g*64+b]);
        float su = 1.f/(sqrtf(nu)+1e-12f);
        float s=0;
        #pragma unroll
        for (int q=0;q<4;q++) s += __ldcg(&up[tid*4+q])*su*__ldcg(&wp[tid*4+q]);
        red[tid]=s; __syncthreads();
        for (int st=128;st>0;st>>=1){ if(tid<st) red[tid]+=red[tid+st]; __syncthreads(); }
        if (tid==0) d_rsigma[g] = 1.f/red[0];
    }
}

__device__ __forceinline__ void split1(float v, __nv_bfloat16& h, __nv_bfloat16& l) {
    h = __float2bfloat16_rn(v);
    l = __float2bfloat16_rn(v - __bfloat162float(h));
}
__device__ __forceinline__ uint32_t s2u(const void* p) {
    uint32_t a;
    asm("{.reg .u64 t; cvta.to.shared.u64 t, %1; cvt.u32.u64 %0, t;}" : "=r"(a) : "l"(p));
    return a;
}
#define CP16(d,s) asm volatile("cp.async.cg.shared.global [%0], [%1], 16;" :: "r"(d), "l"(s))
#define CPC() asm volatile("cp.async.commit_group;")
#define CPW1() asm volatile("cp.async.wait_group 1;")
#define CPW0() asm volatile("cp.async.wait_group 0;")
#define LDSM4(r0,r1,r2,r3,a) asm volatile("ldmatrix.sync.aligned.m8n8.x4.shared.b16 {%0,%1,%2,%3}, [%4];" \
    : "=r"(r0),"=r"(r1),"=r"(r2),"=r"(r3) : "r"(a))
#define MMA(d,a,b0,b1) asm volatile( \
    "mma.sync.aligned.m16n8k16.row.col.f32.bf16.bf16.f32 {%0,%1,%2,%3},{%4,%5,%6,%7},{%8,%9},{%0,%1,%2,%3};" \
    : "+f"(d[0]),"+f"(d[1]),"+f"(d[2]),"+f"(d[3]) \
    : "r"(a[0]),"r"(a[1]),"r"(a[2]),"r"(a[3]),"r"(b0),"r"(b1))

// x split: 8 elems/thread, 16B vector stores
__global__ void splitk8(const float* __restrict__ src, __nv_bfloat16* __restrict__ oh,
                        __nv_bfloat16* __restrict__ ol) {
    size_t i = ((size_t)blockIdx.x*256 + threadIdx.x)*8;
    float4 v0 = *(const float4*)(src + i);
    float4 v1 = *(const float4*)(src + i + 4);
    __nv_bfloat162 h[4], l[4];
    __nv_bfloat16 a,b;
    split1(v0.x,a,b); h[0].x=a; l[0].x=b; split1(v0.y,a,b); h[0].y=a; l[0].y=b;
    split1(v0.z,a,b); h[1].x=a; l[1].x=b; split1(v0.w,a,b); h[1].y=a; l[1].y=b;
    split1(v1.x,a,b); h[2].x=a; l[2].x=b; split1(v1.y,a,b); h[2].y=a; l[2].y=b;
    split1(v1.z,a,b); h[3].x=a; l[3].x=b; split1(v1.w,a,b); h[3].y=a; l[3].y=b;
    *(uint4*)(oh+i) = *(uint4*)h;
    *(uint4*)(ol+i) = *(uint4*)l;
}

__global__ void splitk(const float* __restrict__ src, __nv_bfloat16* __restrict__ oh,
                       __nv_bfloat16* __restrict__ ol, int sidx) {
    float f = sidx >= 0 ? d_rsigma[sidx] : 1.f;
    size_t i = ((size_t)blockIdx.x*256 + threadIdx.x)*4;
    float4 v = *(const float4*)(src + i);
    __nv_bfloat16 h0,l0,h1,l1,h2,l2,h3,l3;
    split1(v.x*f,h0,l0); split1(v.y*f,h1,l1); split1(v.z*f,h2,l2); split1(v.w*f,h3,l3);
    __nv_bfloat162 a,b;
    a.x=h0;a.y=h1;b.x=h2;b.y=h3;
    *(__nv_bfloat162*)(oh+i)=a; *(__nv_bfloat162*)(oh+i+2)=b;
    a.x=l0;a.y=l1;b.x=l2;b.y=l3;
    *(__nv_bfloat162*)(ol+i)=a; *(__nv_bfloat162*)(ol+i+2)=b;
}

__global__ void tsplit(const float* __restrict__ W, __nv_bfloat16* __restrict__ oh,
                       __nv_bfloat16* __restrict__ ol, int sidx) {
    __shared__ float t[32][33];
    float s = sidx >= 0 ? d_rsigma[sidx] : 1.f;
    int x = blockIdx.x*32 + threadIdx.x, y0 = blockIdx.y*32;
    #pragma unroll
    for (int i = threadIdx.y; i < 32; i += 8)
        t[i][threadIdx.x] = W[(size_t)(y0+i)*HD + x];
    __syncthreads();
    int ox = y0 + threadIdx.x, oy0 = blockIdx.x*32;
    #pragma unroll
    for (int i = threadIdx.y; i < 32; i += 8) {
        __nv_bfloat16 h,l; split1(t[threadIdx.x][i]*s,h,l);
        oh[(size_t)(oy0+i)*HD + ox] = h;
        ol[(size_t)(oy0+i)*HD + ox] = l;
    }
}

#define STR 40
// main 128x128-tile GEMM (R12-proven). mode 0/1/2/3 as before.
__global__ void __launch_bounds__(256,2) mmagemm(
    const __nv_bfloat16* __restrict__ Ahh, const __nv_bfloat16* __restrict__ All,
    const __nv_bfloat16* __restrict__ Bhh, const __nv_bfloat16* __restrict__ Bll,
    const float* __restrict__ Add, float* __restrict__ Cf,
    __nv_bfloat16* __restrict__ Oh, __nv_bfloat16* __restrict__ Ol,
    __nv_bfloat16* __restrict__ O2h, __nv_bfloat16* __restrict__ O2l,
    int mode, int jp)
{
    extern __shared__ __nv_bfloat16 smx[];
    const int tid=threadIdx.x, lane=tid&31, wid=tid>>5, wm=wid&3, wn=wid>>2;
    const int m0=blockIdx.y*128, n0=blockIdx.x*128;
    const uint32_t sb=s2u(smx);
    const __nv_bfloat16* srcs[4]={Ahh,All,Bhh,Bll};
    float acc[2][8][4];
    #pragma unroll
    for (int i=0;i<2;i++)
        #pragma unroll
        for (int j=0;j<8;j++)
            #pragma unroll
            for (int q=0;q<4;q++) acc[i][j][q]=0.f;
    const int lr=tid>>1, lc=(tid&1)*16;
    auto ldst = [&](int kt, int st){
        const int k0 = kt*32;
        #pragma unroll
        for (int a=0;a<4;a++) {
            int row = (a<2 ? m0 : n0) + lr;
            const char* s = (const char*)(srcs[a] + (size_t)row*1024 + k0 + lc);
            uint32_t d = sb + (uint32_t)(st*40960 + a*10240 + (lr*STR+lc)*2);
            CP16(d, s); CP16(d+16, s+16);
        }
    };
    ldst(0,0); CPC();
    for (int kt=0; kt<32; kt++) {
        if (kt<31) { ldst(kt+1,(kt+1)&1); CPC(); CPW1(); } else CPW0();
        __syncthreads();
        const uint32_t ab = sb + (kt&1)*40960;
        #pragma unroll
        for (int kh=0;kh<2;kh++) {
            uint32_t ah[2][4], al[2][4];
            #pragma unroll
            for (int ti=0;ti<2;ti++) {
                uint32_t ad = ab + (uint32_t)(((wm*32+ti*16+(lane&15))*STR + kh*16+(lane>>4)*8)*2);
                LDSM4(ah[ti][0],ah[ti][1],ah[ti][2],ah[ti][3], ad);
                LDSM4(al[ti][0],al[ti][1],al[ti][2],al[ti][3], ad+10240);
            }
            #pragma unroll
            for (int q=0;q<4;q++) {
                uint32_t bd = ab + 20480u + (uint32_t)(((wn*64+q*16+(lane&7)+((lane>>4)&1)*8)*STR + kh*16+((lane>>3)&1)*8)*2);
                uint32_t h0,h1,h2,h3,l0,l1,l2,l3;
                LDSM4(h0,h1,h2,h3, bd);
                LDSM4(l0,l1,l2,l3, bd+10240);
                #pragma unroll
                for (int ti=0;ti<2;ti++) {
                    MMA(acc[ti][q*2],   ah[ti], h0,h1);
                    MMA(acc[ti][q*2+1], ah[ti], h2,h3);
                }
                #pragma unroll
                for (int ti=0;ti<2;ti++) {
                    MMA(acc[ti][q*2],   ah[ti], l0,l1);
                    MMA(acc[ti][q*2+1], ah[ti], l2,l3);
                }
                #pragma unroll
                for (int ti=0;ti<2;ti++) {
                    MMA(acc[ti][q*2],   al[ti], h0,h1);
                    MMA(acc[ti][q*2+1], al[ti], h2,h3);
                }
            }
        }
        __syncthreads();
    }
    const int rb0 = m0 + wm*32 + (lane>>2);
    #pragma unroll
    for (int ti=0;ti<2;ti++)
    #pragma unroll
    for (int j=0;j<8;j++)
    #pragma unroll
    for (int hf=0;hf<2;hf++) {
        int r = rb0 + ti*16 + hf*8;
        int c = n0 + wn*64 + j*8 + (lane&3)*2;
        float v0=acc[ti][j][hf*2], v1=acc[ti][j][hf*2+1];
        if (Add) { float2 ad = *(const float2*)(Add+(size_t)r*1024+c); v0+=ad.x; v1+=ad.y; }
        __nv_bfloat16 h0,l0,h1,l1; split1(v0,h0,l0); split1(v1,h1,l1);
        __nv_bfloat162 ph,pl; ph.x=h0;ph.y=h1; pl.x=l0;pl.y=l1;
        if (mode==2) {
            *(__nv_bfloat162*)(Oh+(size_t)r*1024+c)=ph;
            *(__nv_bfloat162*)(Ol+(size_t)r*1024+c)=pl;
            int k=r>>5, b_=r&31;
            size_t o2=(size_t)b_*1024+(size_t)k*8+jp;
            *(float2*)(Cf+o2*1024+c)=make_float2(v0,v1);
            *(__nv_bfloat162*)(O2h+o2*1024+c)=ph;
            *(__nv_bfloat162*)(O2l+o2*1024+c)=pl;
        } else {
            size_t orow=(size_t)r;
            if (mode==1){ int b_=r>>10,t=r&1023,k=t>>3,jj=t&7; orow=(size_t)((((jj<<7)|k)<<5)|b_); }
            if (Cf) *(float2*)(Cf+orow*1024+c)=make_float2(v0,v1);
            if (Oh && (mode!=1 || orow<4096)) {
                *(__nv_bfloat162*)(Oh+orow*1024+c)=ph;
                *(__nv_bfloat162*)(Ol+orow*1024+c)=pl;
            }
        }
    }
}

// 128x64-tile GEMM for 1024^2 ladder squarings: grid (16,8) = 128 CTAs.
// Always mode-3 semantics: Oh/Ol = D split at r; O2h/O2l = D^T split.
// Stage layout (30720B): Ah+0, Al+10240, Bh+20480, Bl+25600.
__global__ void __launch_bounds__(256,2) mmagemm64(
    const __nv_bfloat16* __restrict__ Ahh, const __nv_bfloat16* __restrict__ All,
    const __nv_bfloat16* __restrict__ Bhh, const __nv_bfloat16* __restrict__ Bll,
    __nv_bfloat16* __restrict__ Oh, __nv_bfloat16* __restrict__ Ol,
    __nv_bfloat16* __restrict__ O2h, __nv_bfloat16* __restrict__ O2l)
{
    extern __shared__ __nv_bfloat16 smx[];
    const int tid=threadIdx.x, lane=tid&31, wm=tid>>5;
    const int m0=blockIdx.y*128, n0=blockIdx.x*64;
    const uint32_t sb=s2u(smx);
    float acc[8][4];
    #pragma unroll
    for (int j=0;j<8;j++)
        #pragma unroll
        for (int q=0;q<4;q++) acc[j][q]=0.f;
    const int lr=tid>>1, lc=(tid&1)*16;
    const int br=tid>>2, bc=(tid&3)*8;
    auto ldst = [&](int kt, int st){
        const int k0 = kt*32;
        const char* sa0 = (const char*)(Ahh + (size_t)(m0+lr)*1024 + k0 + lc);
        const char* sa1 = (const char*)(All + (size_t)(m0+lr)*1024 + k0 + lc);
        uint32_t d0 = sb + (uint32_t)(st*30720 + (lr*STR+lc)*2);
        CP16(d0, sa0); CP16(d0+16, sa0+16);
        CP16(d0+10240, sa1); CP16(d0+10240+16, sa1+16);
        const char* sb0 = (const char*)(Bhh + (size_t)(n0+br)*1024 + k0 + bc);
        const char* sb1 = (const char*)(Bll + (size_t)(n0+br)*1024 + k0 + bc);
        uint32_t d1 = sb + (uint32_t)(st*30720 + 20480 + (br*STR+bc)*2);
        CP16(d1, sb0); CP16(d1+5120, sb1);
    };
    ldst(0,0); CPC();
    for (int kt=0; kt<32; kt++) {
        if (kt<31) { ldst(kt+1,(kt+1)&1); CPC(); CPW1(); } else CPW0();
        __syncthreads();
        const uint32_t ab = sb + (kt&1)*30720;
        #pragma unroll
        for (int kh=0;kh<2;kh++) {
            uint32_t ah[4], al[4];
            uint32_t ad = ab + (uint32_t)(((wm*16+(lane&15))*STR + kh*16+(lane>>4)*8)*2);
            LDSM4(ah[0],ah[1],ah[2],ah[3], ad);
            LDSM4(al[0],al[1],al[2],al[3], ad+10240);
            #pragma unroll
            for (int qp=0;qp<2;qp++) {
                uint32_t bh[2][4], bl[2][4];
                #pragma unroll
                for (int e=0;e<2;e++) {
                    int q = qp*2+e;
                    uint32_t bd = ab + 20480u + (uint32_t)(((q*16+(lane&7)+((lane>>4)&1)*8)*STR + kh*16+((lane>>3)&1)*8)*2);
                    LDSM4(bh[e][0],bh[e][1],bh[e][2],bh[e][3], bd);
                    LDSM4(bl[e][0],bl[e][1],bl[e][2],bl[e][3], bd+5120);
                }
                #pragma unroll
                for (int e=0;e<2;e++) {
                    MMA(acc[(qp*2+e)*2],   ah, bh[e][0],bh[e][1]);
                    MMA(acc[(qp*2+e)*2+1], ah, bh[e][2],bh[e][3]);
                }
                #pragma unroll
                for (int e=0;e<2;e++) {
                    MMA(acc[(qp*2+e)*2],   ah, bl[e][0],bl[e][1]);
                    MMA(acc[(qp*2+e)*2+1], ah, bl[e][2],bl[e][3]);
                }
                #pragma unroll
                for (int e=0;e<2;e++) {
                    MMA(acc[(qp*2+e)*2],   al, bh[e][0],bh[e][1]);
                    MMA(acc[(qp*2+e)*2+1], al, bh[e][2],bh[e][3]);
                }
            }
        }
        __syncthreads();
    }
    #pragma unroll
    for (int j=0;j<8;j++)
    #pragma unroll
    for (int hf=0;hf<2;hf++) {
        int r = m0 + wm*16 + (lane>>2) + hf*8;
        int c = n0 + j*8 + (lane&3)*2;
        float v0=acc[j][hf*2], v1=acc[j][hf*2+1];
        __nv_bfloat16 h0,l0,h1,l1; split1(v0,h0,l0); split1(v1,h1,l1);
        __nv_bfloat162 ph,pl; ph.x=h0;ph.y=h1; pl.x=l0;pl.y=l1;
        *(__nv_bfloat162*)(Oh+(size_t)r*1024+c)=ph;
        *(__nv_bfloat162*)(Ol+(size_t)r*1024+c)=pl;
        O2h[(size_t)c*1024+r]=h0;     O2l[(size_t)c*1024+r]=l0;
        O2h[(size_t)(c+1)*1024+r]=h1; O2l[(size_t)(c+1)*1024+r]=l1;
    }
}

__global__ void copy3(float* df, __nv_bfloat16* dh, __nv_bfloat16* dl,
    const float* sf, const __nv_bfloat16* sh, const __nv_bfloat16* sl, int n) {
    int i = blockIdx.x*256 + threadIdx.x;
    if (i < n) { df[i]=sf[i]; dh[i]=sh[i]; dl[i]=sl[i]; }
}
__global__ void zero3(float* f, __nv_bfloat16* h, __nv_bfloat16* l, int n) {
    int i = blockIdx.x*256 + threadIdx.x;
    if (i < n) { f[i]=0.f; h[i]=__float2bfloat16(0.f); l[i]=__float2bfloat16(0.f); }
}

extern "C" void kernel_launch(void* const* d_in, const int* in_sizes, int n_in,
                              void* d_out, int out_size) {
    const float* x  = (const float*)d_in[0];
    const float* WA = (const float*)d_in[1];
    const float* WB = (const float*)d_in[2];
    const float* WC = (const float*)d_in[3];
    float* ys = (float*)d_out;
    float* hs = ys + 33554432UL;
    float* F = nullptr; cudaGetSymbolAddress((void**)&F, g_f);
    __nv_bfloat16* G = nullptr; cudaGetSymbolAddress((void**)&G, g_b);
    float *xb=F+F_XB, *Tf=F+F_T, *Uf=F+F_U;
    __nv_bfloat16* p = G;
    #define NXT(nm,sz) __nv_bfloat16 *nm##h=p, *nm##l=p+(sz); p += 2UL*(sz);
    NXT(X,33554432UL) NXT(WA_,1048576UL) NXT(WB_,1048576UL) NXT(WC_,1048576UL)
    __nv_bfloat16 *Ph[10], *Pl[10];
    Ph[0]=WA_h; Pl[0]=WA_l;
    for (int r=1;r<=9;r++){ Ph[r]=p; Pl[r]=p+1048576UL; p+=2097152UL; }
    NXT(PT0,1048576UL) NXT(PT1,1048576UL)
    NXT(XB0,4194304UL) NXT(S0,4194304UL) NXT(S1,4194304UL)
    __nv_bfloat16 *Th=p, *Tl=p+6291456UL; p+=12582912UL;
    __nv_bfloat16 *Uh=p, *Ul=p+6291456UL; p+=12582912UL;
    NXT(HS,33554432UL)
    #undef NXT

    cudaFuncSetAttribute(mmagemm, cudaFuncAttributeMaxDynamicSharedMemorySize, 81920);
    cudaFuncSetAttribute(mmagemm64, cudaFuncAttributeMaxDynamicSharedMemorySize, 61440);

    // launches 1..5 then xb mmagemm at #6 (ncu -s 5 capture slot)
    spectral3<<<192, 256>>>(WA, WB, WC);
    splitk8<<<16384,256>>>(x, Xh, Xl);
    splitk<<<1024,256>>>(WB, WB_h, WB_l, 1);
    splitk<<<1024,256>>>(WA, WA_h, WA_l, 0);
    splitk<<<1024,256>>>(WC, WC_h, WC_l, 2);
    mmagemm<<<dim3(8,256),256,81920>>>(Xh,Xl, WB_h,WB_l, nullptr, xb, XB0h,XB0l, nullptr,nullptr, 1,0);
    tsplit<<<dim3(32,32), dim3(32,8)>>>(WA, PT0h, PT0l, 0);
    // ladder via 128-CTA N64 kernel with fused transpose, PT ping-pong
    __nv_bfloat16 *pth[2]={PT0h,PT1h}, *ptl[2]={PT0l,PT1l};
    for (int r=1;r<=9;r++) {
        mmagemm64<<<dim3(16,8),256,61440>>>(Ph[r-1],Pl[r-1], pth[(r-1)&1],ptl[(r-1)&1],
            Ph[r],Pl[r], pth[r&1],ptl[r&1]);
    }
    zero3<<<128,256>>>(Tf, Th, Tl, 32768);
    // pass 1: 7 local-scan steps (M=4096); last -> T chunks 1..128
    __nv_bfloat16 *ph_=XB0h, *pl_=XB0l;
    for (int j = 1; j < 8; j++) {
        __nv_bfloat16 *dh = (j==7)?(Th+32768):((j&1)?S1h:S0h);
        __nv_bfloat16 *dl = (j==7)?(Tl+32768):((j&1)?S1l:S0l);
        mmagemm<<<dim3(8,32),256,81920>>>(ph_,pl_, WA_h,WA_l, xb+(size_t)j*4194304UL,
            (j==7)?(Tf+32768):nullptr, dh,dl, nullptr,nullptr, 0,0);
        ph_=dh; pl_=dl;
    }
    // Kogge-Stone over 128 chunks, trimmed grids
    float *cf=Tf, *of=Uf; __nv_bfloat16 *chh=Th,*cll=Tl,*ohh=Uh,*oll=Ul;
    for (int r=0;r<7;r++) {
        int d = 1<<r, n = d*32768;
        int gy = (128 - d + 3) / 4;
        copy3<<<(n+255)/256,256>>>(of, ohh, oll, cf, chh, cll, n);
        mmagemm<<<dim3(8,gy),256,81920>>>(chh,cll, Ph[3+r],Pl[3+r],
            cf+(size_t)n, of+(size_t)n, ohh+(size_t)n, oll+(size_t)n, nullptr,nullptr, 0,0);
        float* tf=cf; cf=of; of=tf;
        __nv_bfloat16 *t1=chh; chh=ohh; ohh=t1;
        __nv_bfloat16 *t2=cll; cll=oll; oll=t2;
    }
    // pass 3: 8 rescan steps, scatter hs
    ph_=chh; pl_=cll;
    for (int j = 0; j < 8; j++) {
        __nv_bfloat16 *dh = (j&1)?S1h:S0h, *dl = (j&1)?S1l:S0l;
        mmagemm<<<dim3(8,32),256,81920>>>(ph_,pl_, WA_h,WA_l, xb+(size_t)j*4194304UL,
            hs, dh,dl, HSh,HSl, 2,j);
        ph_=dh; pl_=dl;
    }
    mmagemm<<<dim3(8,256),256,81920>>>(HSh,HSl, WC_h,WC_l, nullptr, ys, nullptr,nullptr, nullptr,nullptr, 0,0);
    (void)in_sizes; (void)n_in; (void)out_size;
}

// round 17
// speedup vs baseline: 1.4195x; 1.4195x over previous
#include <cuda_runtime.h>
#include <cuda_bf16.h>
#include <cstdint>
#include <math.h>
#define HD 1024
#define NBS 64
#define F_XB 0UL
#define F_T  (F_XB+33554432UL)
#define F_U  (F_T+6291456UL)
#define F_TOT (F_U+6291456UL)
__device__ float g_f[F_TOT];
__device__ __nv_bfloat16 g_b[213909504UL];
__device__ float sp_part3[3*NBS*HD];
__device__ float sp_u3[3*HD], sp_v3[3*HD], sp_w3[3*HD];
__device__ float sp_scale[6];
__device__ float d_rsigma[3];
__device__ unsigned bar_c3[3] = {0,0,0}, bar_g3[3] = {0,0,0};

__device__ __forceinline__ void gbar3(int g) {
    __syncthreads(); __threadfence();
    if (threadIdx.x == 0) {
        unsigned gen = atomicAdd(&bar_g3[g], 0u);
        if (atomicAdd(&bar_c3[g], 1u) == NBS - 1u) {
            bar_c3[g] = 0u; __threadfence(); atomicExch(&bar_g3[g], gen + 1u);
        } else while (atomicAdd(&bar_g3[g], 0u) == gen) __nanosleep(64);
    }
    __syncthreads();
}

__global__ void __launch_bounds__(256) spectral3(const float* __restrict__ WA,
    const float* __restrict__ WB, const float* __restrict__ WC) {
    __shared__ float red[256];
    const int tid = threadIdx.x, g = blockIdx.x >> 6, lb = blockIdx.x & 63;
    const int gtid = lb*256 + tid;
    const float* W = (g==0) ? WA : ((g==1) ? WB : WC);
    float* up = sp_u3 + g*HD;
    float* vp = sp_v3 + g*HD;
    float* wp = sp_w3 + g*HD;
    float* part = sp_part3 + (size_t)g*NBS*HD;
    if (gtid < HD) up[gtid] = 0.03125f;
    if (gtid == 0) sp_scale[g] = 1.f;
    gbar3(g);
    for (int it = 0; it <= 10; it++) {
        {
            const int i0 = lb*16;
            float a0=0,a1=0,a2=0,a3=0;
            for (int i = i0; i < i0+16; i++) {
                float ui = __ldcg(&up[i]);
                const float* Wr = W + (size_t)i*HD;
                a0 += Wr[tid]*ui; a1 += Wr[tid+256]*ui;
                a2 += Wr[tid+512]*ui; a3 += Wr[tid+768]*ui;
            }
            part[lb*HD+tid]=a0; part[lb*HD+tid+256]=a1;
            part[lb*HD+tid+512]=a2; part[lb*HD+tid+768]=a3;
        }
        gbar3(g);
        if (gtid < HD) {
            float s=0;
            for (int b=0;b<NBS;b++) s += __ldcg(&part[b*HD+gtid]);
            vp[gtid] = s * __ldcg(&sp_scale[g]);
        }
        gbar3(g);
        if (lb == 0) {
            float s=0;
            #pragma unroll
            for (int q=0;q<4;q++){ float x=__ldcg(&vp[tid*4+q]); s+=x*x; }
            red[tid]=s; __syncthreads();
            for (int st=128;st>0;st>>=1){ if(tid<st) red[tid]+=red[tid+st]; __syncthreads(); }
            if (tid==0) sp_scale[3+g] = 1.f/(sqrtf(red[0]) + 1e-12f);
        }
        gbar3(g);
        if (it == 10) break;
        {
            float sv = __ldcg(&sp_scale[3+g]);
            const int warp = gtid>>5, lane = gtid&31;
            for (int i = warp; i < HD; i += (NBS*256)/32) {
                const float* Wr = W + (size_t)i*HD;
                float s=0;
                for (int j=lane;j<HD;j+=32) s += Wr[j]*__ldcg(&vp[j]);
                #pragma unroll
                for (int o=16;o;o>>=1) s += __shfl_xor_sync(0xffffffffu,s,o);
                if (lane==0) up[i] = s*sv;
            }
        }
        gbar3(g);
        if (lb == 0) {
            float s=0;
            #pragma unroll
            for (int q=0;q<4;q++){ float x=__ldcg(&up[tid*4+q]); s+=x*x; }
            red[tid]=s; __syncthreads();
            for (int st=128;st>0;st>>=1){ if(tid<st) red[tid]+=red[tid+st]; __syncthreads(); }
            if (tid==0) sp_scale[g] = 1.f/(sqrtf(red[0]) + 1e-12f);
        }
        gbar3(g);
    }
    {
        float sv = __ldcg(&sp_scale[3+g]);
        const int warp = gtid>>5, lane = gtid&31;
        for (int i = warp; i < HD; i += (NBS*256)/32) {
            const float* Wr = W + (size_t)i*HD;
            float s=0;
            for (int j=lane;j<HD;j+=32) s += Wr[j]*__ldcg(&vp[j]);
            #pragma unroll
            for (int o=16;o;o>>=1) s += __shfl_xor_sync(0xffffffffu,s,o);
            if (lane==0) wp[i] = s*sv;
        }
    }
    gbar3(g);
    if (lb == 0) {
        float su = __ldcg(&sp_scale[g]);
        float s=0;
        #pragma unroll
        for (int q=0;q<4;q++) s += __ldcg(&up[tid*4+q])*su*__ldcg(&wp[tid*4+q]);
        red[tid]=s; __syncthreads();
        for (int st=128;st>0;st>>=1){ if(tid<st) red[tid]+=red[tid+st]; __syncthreads(); }
        if (tid==0) d_rsigma[g] = 1.f/red[0];
    }
}

__device__ __forceinline__ void split1(float v, __nv_bfloat16& h, __nv_bfloat16& l) {
    h = __float2bfloat16_rn(v);
    l = __float2bfloat16_rn(v - __bfloat162float(h));
}
__device__ __forceinline__ uint32_t s2u(const void* p) {
    uint32_t a;
    asm("{.reg .u64 t; cvta.to.shared.u64 t, %1; cvt.u32.u64 %0, t;}" : "=r"(a) : "l"(p));
    return a;
}
#define CP16(d,s) asm volatile("cp.async.cg.shared.global [%0], [%1], 16;" :: "r"(d), "l"(s))
#define CPC() asm volatile("cp.async.commit_group;")
#define CPW1() asm volatile("cp.async.wait_group 1;")
#define CPW0() asm volatile("cp.async.wait_group 0;")
#define LDSM4(r0,r1,r2,r3,a) asm volatile("ldmatrix.sync.aligned.m8n8.x4.shared.b16 {%0,%1,%2,%3}, [%4];" \
    : "=r"(r0),"=r"(r1),"=r"(r2),"=r"(r3) : "r"(a))
#define MMA(d,a,b0,b1) asm volatile( \
    "mma.sync.aligned.m16n8k16.row.col.f32.bf16.bf16.f32 {%0,%1,%2,%3},{%4,%5,%6,%7},{%8,%9},{%0,%1,%2,%3};" \
    : "+f"(d[0]),"+f"(d[1]),"+f"(d[2]),"+f"(d[3]) \
    : "r"(a[0]),"r"(a[1]),"r"(a[2]),"r"(a[3]),"r"(b0),"r"(b1))

// x split: 8 elems/thread, 16B vector stores (x needs no sigma scale)
__global__ void splitk8(const float* __restrict__ src, __nv_bfloat16* __restrict__ oh,
                        __nv_bfloat16* __restrict__ ol) {
    size_t i = ((size_t)blockIdx.x*256 + threadIdx.x)*8;
    float4 v0 = *(const float4*)(src + i);
    float4 v1 = *(const float4*)(src + i + 4);
    __nv_bfloat162 h[4], l[4];
    __nv_bfloat16 a,b;
    split1(v0.x,a,b); h[0].x=a; l[0].x=b; split1(v0.y,a,b); h[0].y=a; l[0].y=b;
    split1(v0.z,a,b); h[1].x=a; l[1].x=b; split1(v0.w,a,b); h[1].y=a; l[1].y=b;
    split1(v1.x,a,b); h[2].x=a; l[2].x=b; split1(v1.y,a,b); h[2].y=a; l[2].y=b;
    split1(v1.z,a,b); h[3].x=a; l[3].x=b; split1(v1.w,a,b); h[3].y=a; l[3].y=b;
    *(uint4*)(oh+i) = *(uint4*)h;
    *(uint4*)(ol+i) = *(uint4*)l;
}

__global__ void splitk(const float* __restrict__ src, __nv_bfloat16* __restrict__ oh,
                       __nv_bfloat16* __restrict__ ol, int sidx) {
    float f = sidx >= 0 ? d_rsigma[sidx] : 1.f;
    size_t i = ((size_t)blockIdx.x*256 + threadIdx.x)*4;
    float4 v = *(const float4*)(src + i);
    __nv_bfloat16 h0,l0,h1,l1,h2,l2,h3,l3;
    split1(v.x*f,h0,l0); split1(v.y*f,h1,l1); split1(v.z*f,h2,l2); split1(v.w*f,h3,l3);
    __nv_bfloat162 a,b;
    a.x=h0;a.y=h1;b.x=h2;b.y=h3;
    *(__nv_bfloat162*)(oh+i)=a; *(__nv_bfloat162*)(oh+i+2)=b;
    a.x=l0;a.y=l1;b.x=l2;b.y=l3;
    *(__nv_bfloat162*)(ol+i)=a; *(__nv_bfloat162*)(ol+i+2)=b;
}

__global__ void tsplit(const float* __restrict__ W, __nv_bfloat16* __restrict__ oh,
                       __nv_bfloat16* __restrict__ ol, int sidx) {
    __shared__ float t[32][33];
    float s = sidx >= 0 ? d_rsigma[sidx] : 1.f;
    int x = blockIdx.x*32 + threadIdx.x, y0 = blockIdx.y*32;
    #pragma unroll
    for (int i = threadIdx.y; i < 32; i += 8)
        t[i][threadIdx.x] = W[(size_t)(y0+i)*HD + x];
    __syncthreads();
    int ox = y0 + threadIdx.x, oy0 = blockIdx.x*32;
    #pragma unroll
    for (int i = threadIdx.y; i < 32; i += 8) {
        __nv_bfloat16 h,l; split1(t[threadIdx.x][i]*s,h,l);
        oh[(size_t)(oy0+i)*HD + ox] = h;
        ol[(size_t)(oy0+i)*HD + ox] = l;
    }
}

#define STR 40
// mode 0: Cf?/Oh? at r. mode 1: xb scatter (CHUNK=8; bf16 if scan row<4096).
// mode 2: pass3 hs. mode 3: Oh/Ol at r AND O2h/O2l transposed (ladder fused transpose).
__global__ void __launch_bounds__(256,2) mmagemm(
    const __nv_bfloat16* __restrict__ Ahh, const __nv_bfloat16* __restrict__ All,
    const __nv_bfloat16* __restrict__ Bhh, const __nv_bfloat16* __restrict__ Bll,
    const float* __restrict__ Add, float* __restrict__ Cf,
    __nv_bfloat16* __restrict__ Oh, __nv_bfloat16* __restrict__ Ol,
    __nv_bfloat16* __restrict__ O2h, __nv_bfloat16* __restrict__ O2l,
    int mode, int jp)
{
    extern __shared__ __nv_bfloat16 smx[];
    const int tid=threadIdx.x, lane=tid&31, wid=tid>>5, wm=wid&3, wn=wid>>2;
    const int m0=blockIdx.y*128, n0=blockIdx.x*128;
    const uint32_t sb=s2u(smx);
    const __nv_bfloat16* srcs[4]={Ahh,All,Bhh,Bll};
    float acc[2][8][4];
    #pragma unroll
    for (int i=0;i<2;i++)
        #pragma unroll
        for (int j=0;j<8;j++)
            #pragma unroll
            for (int q=0;q<4;q++) acc[i][j][q]=0.f;
    const int lr=tid>>1, lc=(tid&1)*16;
    auto ldst = [&](int kt, int st){
        const int k0 = kt*32;
        #pragma unroll
        for (int a=0;a<4;a++) {
            int row = (a<2 ? m0 : n0) + lr;
            const char* s = (const char*)(srcs[a] + (size_t)row*1024 + k0 + lc);
            uint32_t d = sb + (uint32_t)(st*40960 + a*10240 + (lr*STR+lc)*2);
            CP16(d, s); CP16(d+16, s+16);
        }
    };
    ldst(0,0); CPC();
    for (int kt=0; kt<32; kt++) {
        if (kt<31) { ldst(kt+1,(kt+1)&1); CPC(); CPW1(); } else CPW0();
        __syncthreads();
        const uint32_t ab = sb + (kt&1)*40960;
        #pragma unroll
        for (int kh=0;kh<2;kh++) {
            uint32_t ah[2][4], al[2][4];
            #pragma unroll
            for (int ti=0;ti<2;ti++) {
                uint32_t ad = ab + (uint32_t)(((wm*32+ti*16+(lane&15))*STR + kh*16+(lane>>4)*8)*2);
                LDSM4(ah[ti][0],ah[ti][1],ah[ti][2],ah[ti][3], ad);
                LDSM4(al[ti][0],al[ti][1],al[ti][2],al[ti][3], ad+10240);
            }
            #pragma unroll
            for (int q=0;q<4;q++) {
                uint32_t bd = ab + 20480u + (uint32_t)(((wn*64+q*16+(lane&7)+((lane>>4)&1)*8)*STR + kh*16+((lane>>3)&1)*8)*2);
                uint32_t h0,h1,h2,h3,l0,l1,l2,l3;
                LDSM4(h0,h1,h2,h3, bd);
                LDSM4(l0,l1,l2,l3, bd+10240);
                #pragma unroll
                for (int ti=0;ti<2;ti++) {
                    MMA(acc[ti][q*2],   ah[ti], h0,h1);
                    MMA(acc[ti][q*2+1], ah[ti], h2,h3);
                }
                #pragma unroll
                for (int ti=0;ti<2;ti++) {
                    MMA(acc[ti][q*2],   ah[ti], l0,l1);
                    MMA(acc[ti][q*2+1], ah[ti], l2,l3);
                }
                #pragma unroll
                for (int ti=0;ti<2;ti++) {
                    MMA(acc[ti][q*2],   al[ti], h0,h1);
                    MMA(acc[ti][q*2+1], al[ti], h2,h3);
                }
            }
        }
        __syncthreads();
    }
    const int rb0 = m0 + wm*32 + (lane>>2);
    #pragma unroll
    for (int ti=0;ti<2;ti++)
    #pragma unroll
    for (int j=0;j<8;j++)
    #pragma unroll
    for (int hf=0;hf<2;hf++) {
        int r = rb0 + ti*16 + hf*8;
        int c = n0 + wn*64 + j*8 + (lane&3)*2;
        float v0=acc[ti][j][hf*2], v1=acc[ti][j][hf*2+1];
        if (Add) { float2 ad = *(const float2*)(Add+(size_t)r*1024+c); v0+=ad.x; v1+=ad.y; }
        __nv_bfloat16 h0,l0,h1,l1; split1(v0,h0,l0); split1(v1,h1,l1);
        __nv_bfloat162 ph,pl; ph.x=h0;ph.y=h1; pl.x=l0;pl.y=l1;
        if (mode==2) {
            *(__nv_bfloat162*)(Oh+(size_t)r*1024+c)=ph;
            *(__nv_bfloat162*)(Ol+(size_t)r*1024+c)=pl;
            int k=r>>5, b_=r&31;
            size_t o2=(size_t)b_*1024+(size_t)k*8+jp;
            *(float2*)(Cf+o2*1024+c)=make_float2(v0,v1);
            *(__nv_bfloat162*)(O2h+o2*1024+c)=ph;
            *(__nv_bfloat162*)(O2l+o2*1024+c)=pl;
        } else if (mode==3) {
            *(__nv_bfloat162*)(Oh+(size_t)r*1024+c)=ph;
            *(__nv_bfloat162*)(Ol+(size_t)r*1024+c)=pl;
            O2h[(size_t)c*1024+r]=h0;     O2l[(size_t)c*1024+r]=l0;
            O2h[(size_t)(c+1)*1024+r]=h1; O2l[(size_t)(c+1)*1024+r]=l1;
        } else {
            size_t orow=(size_t)r;
            if (mode==1){ int b_=r>>10,t=r&1023,k=t>>3,jj=t&7; orow=(size_t)((((jj<<7)|k)<<5)|b_); }
            if (Cf) *(float2*)(Cf+orow*1024+c)=make_float2(v0,v1);
            if (Oh && (mode!=1 || orow<4096)) {
                *(__nv_bfloat162*)(Oh+orow*1024+c)=ph;
                *(__nv_bfloat162*)(Ol+orow*1024+c)=pl;
            }
        }
    }
}

__global__ void copy3(float* df, __nv_bfloat16* dh, __nv_bfloat16* dl,
    const float* sf, const __nv_bfloat16* sh, const __nv_bfloat16* sl, int n) {
    int i = blockIdx.x*256 + threadIdx.x;
    if (i < n) { df[i]=sf[i]; dh[i]=sh[i]; dl[i]=sl[i]; }
}
__global__ void zero3(float* f, __nv_bfloat16* h, __nv_bfloat16* l, int n) {
    int i = blockIdx.x*256 + threadIdx.x;
    if (i < n) { f[i]=0.f; h[i]=__float2bfloat16(0.f); l[i]=__float2bfloat16(0.f); }
}

extern "C" void kernel_launch(void* const* d_in, const int* in_sizes, int n_in,
                              void* d_out, int out_size) {
    const float* x  = (const float*)d_in[0];
    const float* WA = (const float*)d_in[1];
    const float* WB = (const float*)d_in[2];
    const float* WC = (const float*)d_in[3];
    float* ys = (float*)d_out;
    float* hs = ys + 33554432UL;
    float* F = nullptr; cudaGetSymbolAddress((void**)&F, g_f);
    __nv_bfloat16* G = nullptr; cudaGetSymbolAddress((void**)&G, g_b);
    float *xb=F+F_XB, *Tf=F+F_T, *Uf=F+F_U;
    __nv_bfloat16* p = G;
    #define NXT(nm,sz) __nv_bfloat16 *nm##h=p, *nm##l=p+(sz); p += 2UL*(sz);
    NXT(X,33554432UL) NXT(WA_,1048576UL) NXT(WB_,1048576UL) NXT(WC_,1048576UL)
    __nv_bfloat16 *Ph[10], *Pl[10];
    Ph[0]=WA_h; Pl[0]=WA_l;
    for (int r=1;r<=9;r++){ Ph[r]=p; Pl[r]=p+1048576UL; p+=2097152UL; }
    NXT(PT0,1048576UL) NXT(PT1,1048576UL)
    NXT(XB0,4194304UL) NXT(S0,4194304UL) NXT(S1,4194304UL)
    __nv_bfloat16 *Th=p, *Tl=p+6291456UL; p+=12582912UL;
    __nv_bfloat16 *Uh=p, *Ul=p+6291456UL; p+=12582912UL;
    NXT(HS,33554432UL)
    #undef NXT

    cudaFuncSetAttribute(mmagemm, cudaFuncAttributeMaxDynamicSharedMemorySize, 81920);

    // launches 1..5 are non-GEMM; xb mmagemm is launch #6 (ncu capture slot)
    spectral3<<<192, 256>>>(WA, WB, WC);
    splitk8<<<16384,256>>>(x, Xh, Xl);
    splitk<<<1024,256>>>(WB, WB_h, WB_l, 1);
    splitk<<<1024,256>>>(WA, WA_h, WA_l, 0);
    splitk<<<1024,256>>>(WC, WC_h, WC_l, 2);
    mmagemm<<<dim3(8,256),256,81920>>>(Xh,Xl, WB_h,WB_l, nullptr, xb, XB0h,XB0l, nullptr,nullptr, 1,0);
    tsplit<<<dim3(32,32), dim3(32,8)>>>(WA, PT0h, PT0l, 0);
    // ladder with fused transpose epilogue (mode 3), PT ping-pong
    __nv_bfloat16 *pth[2]={PT0h,PT1h}, *ptl[2]={PT0l,PT1l};
    for (int r=1;r<=9;r++) {
        mmagemm<<<dim3(8,8),256,81920>>>(Ph[r-1],Pl[r-1], pth[(r-1)&1],ptl[(r-1)&1],
            nullptr, nullptr, Ph[r],Pl[r], pth[r&1],ptl[r&1], 3,0);
    }
    zero3<<<128,256>>>(Tf, Th, Tl, 32768);
    // pass 1: 7 local-scan steps (M=4096); last -> T chunks 1..128
    __nv_bfloat16 *ph_=XB0h, *pl_=XB0l;
    for (int j = 1; j < 8; j++) {
        __nv_bfloat16 *dh = (j==7)?(Th+32768):((j&1)?S1h:S0h);
        __nv_bfloat16 *dl = (j==7)?(Tl+32768):((j&1)?S1l:S0l);
        mmagemm<<<dim3(8,32),256,81920>>>(ph_,pl_, WA_h,WA_l, xb+(size_t)j*4194304UL,
            (j==7)?(Tf+32768):nullptr, dh,dl, nullptr,nullptr, 0,0);
        ph_=dh; pl_=dl;
    }
    // Kogge-Stone over 128 chunks, trimmed grids
    float *cf=Tf, *of=Uf; __nv_bfloat16 *chh=Th,*cll=Tl,*ohh=Uh,*oll=Ul;
    for (int r=0;r<7;r++) {
        int d = 1<<r, n = d*32768;
        int gy = (128 - d + 3) / 4;
        copy3<<<(n+255)/256,256>>>(of, ohh, oll, cf, chh, cll, n);
        mmagemm<<<dim3(8,gy),256,81920>>>(chh,cll, Ph[3+r],Pl[3+r],
            cf+(size_t)n, of+(size_t)n, ohh+(size_t)n, oll+(size_t)n, nullptr,nullptr, 0,0);
        float* tf=cf; cf=of; of=tf;
        __nv_bfloat16 *t1=chh; chh=ohh; ohh=t1;
        __nv_bfloat16 *t2=cll; cll=oll; oll=t2;
    }
    // pass 3: 8 rescan steps with true inits, scatter hs
    ph_=chh; pl_=cll;
    for (int j = 0; j < 8; j++) {
        __nv_bfloat16 *dh = (j&1)?S1h:S0h, *dl = (j&1)?S1l:S0l;
        mmagemm<<<dim3(8,32),256,81920>>>(ph_,pl_, WA_h,WA_l, xb+(size_t)j*4194304UL,
            hs, dh,dl, HSh,HSl, 2,j);
        ph_=dh; pl_=dl;
    }
    mmagemm<<<dim3(8,256),256,81920>>>(HSh,HSl, WC_h,WC_l, nullptr, ys, nullptr,nullptr, nullptr,nullptr, 0,0);
    (void)in_sizes; (void)n_in; (void)out_size;
}